// round 11
// baseline (speedup 1.0000x reference)
#include <cuda_runtime.h>
#include <cuda_fp16.h>
#include <math.h>
#include <stdint.h>

#define T_LEN  2048
#define BSZ    2
#define E_DIM  1024
#define H_NUM  16
#define D_DIM  64
#define PLEN   32
#define BH     32
#define SCH    32               // state chunk
#define NSC    (T_LEN/SCH)      // 64
#define SCALING 0.125f
#define BETA    0.6931471805599453f

#define MROWS  (T_LEN*BSZ)      // 4096
#define NE     (E_DIM*E_DIM)

// ------------------------- scratch -----------------------------------------
__device__ float g_pq   [BH*PLEN*D_DIM];
__device__ float g_q    [BH*T_LEN*D_DIM];
__device__ float g_kp   [BH*T_LEN*D_DIM];
__device__ float g_kv   [BH*T_LEN*D_DIM];
__device__ float g_pattn[BH*T_LEN*PLEN];
__device__ float g_S    [BH*NSC*D_DIM*PLEN];

__device__ __half g_Ah  [MROWS*E_DIM];
__device__ __half g_PQh [64*E_DIM];
__device__ __half g_W4h [4*NE];          // Wq, Wpc, Wc, Wpq
__device__ __half g_WOh [NE];
__device__ __half g_ATh [MROWS*E_DIM];

// ------------------------- helpers -----------------------------------------
__device__ __forceinline__ uint32_t smem_u32(const void* p) {
    uint32_t a;
    asm("{ .reg .u64 t; cvta.to.shared.u64 t, %1; cvt.u32.u64 %0, t; }"
        : "=r"(a) : "l"(p));
    return a;
}
__device__ __forceinline__ uint32_t sw128(uint32_t off) {
    return off ^ ((off >> 3) & 0x70);
}
__device__ __forceinline__ void ldsm_x4(uint32_t* r, uint32_t addr) {
    asm volatile("ldmatrix.sync.aligned.m8n8.x4.shared.b16 {%0,%1,%2,%3}, [%4];"
                 : "=r"(r[0]), "=r"(r[1]), "=r"(r[2]), "=r"(r[3]) : "r"(addr));
}
__device__ __forceinline__ void mma16816(float* c, const uint32_t* a, const uint32_t* b) {
    asm volatile("mma.sync.aligned.m16n8k16.row.col.f32.f16.f16.f32 "
                 "{%0,%1,%2,%3}, {%4,%5,%6,%7}, {%8,%9}, {%0,%1,%2,%3};"
                 : "+f"(c[0]), "+f"(c[1]), "+f"(c[2]), "+f"(c[3])
                 : "r"(a[0]), "r"(a[1]), "r"(a[2]), "r"(a[3]), "r"(b[0]), "r"(b[1]));
}
__device__ __forceinline__ void cp16(uint32_t dst, const void* src, int sz) {
    asm volatile("cp.async.cg.shared.global [%0], [%1], 16, %2;"
                 :: "r"(dst), "l"(src), "r"(sz));
}
__device__ __forceinline__ void cp_commit() {
    asm volatile("cp.async.commit_group;" ::: "memory");
}
__device__ __forceinline__ void cp_wait1() {
    asm volatile("cp.async.wait_group 1;" ::: "memory");
}
__device__ __forceinline__ void cp_wait0() {
    asm volatile("cp.async.wait_group 0;" ::: "memory");
}

// ---- packed f32x2 ----
__device__ __forceinline__ uint64_t pack2(float x, float y) {
    uint64_t r;
    asm("mov.b64 %0, {%1, %2};" : "=l"(r) : "f"(x), "f"(y));
    return r;
}
__device__ __forceinline__ void unpack2(uint64_t v, float& x, float& y) {
    asm("mov.b64 {%0, %1}, %2;" : "=f"(x), "=f"(y) : "l"(v));
}
__device__ __forceinline__ uint64_t fma2(uint64_t a, uint64_t b, uint64_t c) {
    uint64_t d;
    asm("fma.rn.f32x2 %0, %1, %2, %3;" : "=l"(d) : "l"(a), "l"(b), "l"(c));
    return d;
}

// ------------------------- merged fp32 -> fp16 converter -------------------
#define NCVT 7
struct CvtArgs {
    const float4* s[NCVT];
    __half2*      h[NCVT];
    int           end[NCVT];
};

__global__ __launch_bounds__(256)
void cvt_all(CvtArgs A)
{
    int gi = blockIdx.x * 256 + threadIdx.x;
    int seg = 0;
    while (seg < NCVT && gi >= A.end[seg]) seg++;
    if (seg >= NCVT) return;
    int i = gi - (seg ? A.end[seg - 1] : 0);

    float4 v = A.s[seg][i];
    A.h[seg][2 * i]     = __half2(__float2half_rn(v.x), __float2half_rn(v.y));
    A.h[seg][2 * i + 1] = __half2(__float2half_rn(v.z), __float2half_rn(v.w));
}

// ------------------------- pipelined fp16 GEMM ------------------------------
__device__ __forceinline__ void g_load_stage(
    uint32_t sb, int slot,
    const __half* Ah, const __half* Bh,
    int bm, int bn, int kb, int M, int tid)
{
    const uint32_t abase = sb + slot * 32768;
    const uint32_t bbase = abase + 16384;
    const int c  = tid & 7;
    const int r0 = tid >> 3;
    const int kc = kb + c * 8;
#pragma unroll
    for (int ii = 0; ii < 4; ii++) {
        int r = r0 + ii * 32;
        uint32_t so = sw128((uint32_t)(r * 128 + c * 16));
        int m = bm + r;
        int mc = (m < M) ? m : (M - 1);
        cp16(abase + so, Ah + (size_t)mc * E_DIM + kc, (m < M) ? 16 : 0);
        cp16(bbase + so, Bh + (size_t)(bn + r) * E_DIM + kc, 16);
    }
}

__global__ __launch_bounds__(256, 2)
void gemm_mma(const __half* __restrict__ A0, const __half* __restrict__ A3,
              const __half* __restrict__ W,
              const float* b0, const float* b1, const float* b2, const float* b3,
              float* o0, float* o1, float* o2, float* o3,
              float s0, float s1, float s2, float s3,
              int M0, int M3, int mode, int Trows0, int Trows3)
{
    extern __shared__ char smem[];
    const uint32_t sb = smem_u32(smem);

    const int tid = threadIdx.x, wid = tid >> 5, lane = tid & 31;
    const int bm = blockIdx.y * 128, bn = blockIdx.x * 128;
    const int z = blockIdx.z;
    const int M     = (z == 3) ? M3 : M0;
    const int Trows = (z == 3) ? Trows3 : Trows0;
    if (bm >= M) return;
    const __half* Ah = (z == 3) ? A3 : A0;
    const __half* wh = W + (size_t)z * NE;
    const float* bias = (z == 0) ? b0 : ((z == 1) ? b1 : ((z == 2) ? b2 : b3));
    float* out        = (z == 0) ? o0 : ((z == 1) ? o1 : ((z == 2) ? o2 : o3));
    const float scale = (z == 0) ? s0 : ((z == 1) ? s1 : ((z == 2) ? s2 : s3));

    const int warpM = (wid >> 2) * 64;
    const int warpN = (wid & 3) * 32;
    const int li = lane >> 3, lr = lane & 7;

    float acc[4][4][4];
#pragma unroll
    for (int i = 0; i < 4; i++)
#pragma unroll
        for (int j = 0; j < 4; j++)
#pragma unroll
            for (int k = 0; k < 4; k++) acc[i][j][k] = 0.f;

    const int NK = E_DIM / 64;
    g_load_stage(sb, 0, Ah, wh, bm, bn, 0, M, tid);
    cp_commit();
    g_load_stage(sb, 1, Ah, wh, bm, bn, 64, M, tid);
    cp_commit();

    int slot = 0, next = 2;
    for (int ks = 0; ks < NK; ks++) {
        if (ks + 1 < NK) cp_wait1(); else cp_wait0();
        __syncthreads();
        if (ks + 2 < NK) {
            g_load_stage(sb, next, Ah, wh, bm, bn, (ks + 2) * 64, M, tid);
            cp_commit();
            if (++next == 3) next = 0;
        }

        const uint32_t abase = sb + slot * 32768;
        const uint32_t bbase = abase + 16384;
        if (++slot == 3) slot = 0;
#pragma unroll
        for (int kk = 0; kk < 4; kk++) {
            uint32_t bfr[2][4];
            const uint32_t kb2 = (uint32_t)(kk * 32 + (li & 1) * 16);
#pragma unroll
            for (int jn = 0; jn < 2; jn++) {
                uint32_t off = (uint32_t)((warpN + jn * 16 + (li >> 1) * 8 + lr) * 128) + kb2;
                ldsm_x4(bfr[jn], bbase + sw128(off));
            }
            const uint32_t ka = (uint32_t)(kk * 32 + (li >> 1) * 16);
#pragma unroll
            for (int i = 0; i < 4; i++) {
                uint32_t ah[4];
                uint32_t off = (uint32_t)((warpM + i * 16 + (li & 1) * 8 + lr) * 128) + ka;
                ldsm_x4(ah, abase + sw128(off));
#pragma unroll
                for (int j = 0; j < 4; j++)
                    mma16816(acc[i][j], ah, &bfr[j >> 1][(j & 1) * 2]);
            }
        }
    }

    const int g = lane >> 2, tg = lane & 3;
#pragma unroll
    for (int i = 0; i < 4; i++) {
#pragma unroll
        for (int j = 0; j < 4; j++) {
            int n0 = bn + warpN + j * 8 + tg * 2;
            float bx = bias[n0], by = bias[n0 + 1];
#pragma unroll
            for (int half = 0; half < 2; half++) {
                int m = bm + warpM + i * 16 + g + half * 8;
                if (m >= M) continue;
                float2 v;
                v.x = (acc[i][j][half * 2 + 0] + bx) * scale;
                v.y = (acc[i][j][half * 2 + 1] + by) * scale;
                if (mode == 0) {
                    *(float2*)&out[(size_t)m * E_DIM + n0] = v;
                } else {
                    int t = m >> 1, b = m & 1;
                    int h = n0 >> 6, d = n0 & 63;
                    *(float2*)&out[(size_t)((b * 16 + h) * Trows + t) * 64 + d] = v;
                }
            }
        }
    }
}

// ------------- merged pattn (softplus) + TWO 32-row local states ------------
__global__ __launch_bounds__(256, 2)
void pattn_local()
{
    const int bx = blockIdx.x, bh = blockIdx.y;
    extern __shared__ float sm[];
    float* kps = sm;                   // 64 x 66
    float* pqs = kps + 64 * 66;        // 32 x 66
    float* kvs = pqs + 32 * 66;        // 64 x 64
    float* ps  = kvs + 64 * 64;        // 64 x 32
    const size_t base = (size_t)bh * T_LEN + bx * 64;
    const int tid = threadIdx.x;

    for (int i = tid; i < 64 * 64; i += 256) {
        int s = i >> 6, d = i & 63;
        kps[s * 66 + d] = g_kp[(base + s) * 64 + d];
        kvs[i] = g_kv[(base + s) * 64 + d];
    }
    for (int i = tid; i < PLEN * 64; i += 256) {
        int p = i >> 6, d = i & 63;
        pqs[p * 66 + d] = g_pq[(size_t)bh * PLEN * D_DIM + i];
    }
    __syncthreads();

    // pattn (packed f32x2 dots)
    {
        const int t  = tid >> 2;
        const int p0 = (tid & 3) * 8;
        uint64_t acc[8];
#pragma unroll
        for (int p = 0; p < 8; p++) acc[p] = 0ull;
#pragma unroll
        for (int half = 0; half < 2; half++) {
            uint64_t kpp[16];
            const uint64_t* kr = (const uint64_t*)&kps[t * 66 + half * 32];
#pragma unroll
            for (int k = 0; k < 16; k++) kpp[k] = kr[k];
#pragma unroll
            for (int p = 0; p < 8; p++) {
                const uint64_t* pq = (const uint64_t*)&pqs[(p0 + p) * 66 + half * 32];
#pragma unroll
                for (int k = 0; k < 16; k++) acc[p] = fma2(kpp[k], pq[k], acc[p]);
            }
        }
#pragma unroll
        for (int p = 0; p < 8; p++) {
            float x, y;
            unpack2(acc[p], x, y);
            float zz = BETA * (x + y);
            float sp = (fmaxf(zz, 0.f) + log1pf(expf(-fabsf(zz)))) * (1.0f / BETA);
            ps[t * 32 + p0 + p] = sp;
            g_pattn[(base + t) * PLEN + p0 + p] = sp;
        }
    }
    __syncthreads();

    // local states (packed applies)
    {
        const int d  = tid >> 2;
        const int j0 = (tid & 3) * 8;
        uint64_t a0[4] = {0ull, 0ull, 0ull, 0ull};
        uint64_t a1[4] = {0ull, 0ull, 0ull, 0ull};
        for (int s = 0; s < 32; s++) {
            uint64_t ap = pack2(kvs[s * 64 + d], kvs[s * 64 + d]);
            const uint64_t* pr = (const uint64_t*)&ps[s * 32 + j0];
#pragma unroll
            for (int k = 0; k < 4; k++) a0[k] = fma2(ap, pr[k], a0[k]);
        }
        for (int s = 32; s < 64; s++) {
            uint64_t ap = pack2(kvs[s * 64 + d], kvs[s * 64 + d]);
            const uint64_t* pr = (const uint64_t*)&ps[s * 32 + j0];
#pragma unroll
            for (int k = 0; k < 4; k++) a1[k] = fma2(ap, pr[k], a1[k]);
        }
        float* o0 = &g_S[((size_t)bh * NSC + 2 * bx)     * 2048];
        float* o1 = &g_S[((size_t)bh * NSC + 2 * bx + 1) * 2048];
#pragma unroll
        for (int k = 0; k < 4; k++) {
            float x, y;
            unpack2(a0[k], x, y);
            o0[d * 32 + j0 + 2 * k]     = x;
            o0[d * 32 + j0 + 2 * k + 1] = y;
            unpack2(a1[k], x, y);
            o1[d * 32 + j0 + 2 * k]     = x;
            o1[d * 32 + j0 + 2 * k + 1] = y;
        }
    }
}

// ------------------- exclusive prefix scan over 64 chunks ------------------
__global__ __launch_bounds__(256)
void scan_states()
{
    const int gi = blockIdx.x * 256 + threadIdx.x;
    const int bh = gi >> 11;
    const int e  = gi & 2047;
    float run = 0.f;
    float* p = &g_S[(size_t)bh * NSC * 2048 + e];
    for (int c = 0; c < NSC; c++) {
        float v = p[c * 2048];
        p[c * 2048] = run;
        run += v;
    }
}

// ------------------- fused pass1 + softmax + pass2 (SCH=32, packed f32x2) ---
__global__ __launch_bounds__(256, 2)
void fused_pass()
{
    const int bx = blockIdx.x, bh = blockIdx.y;
    extern __shared__ float sm[];
    float* qs  = sm;                 // 64 x 66
    float* kvs = qs  + 64 * 66;      // 64 x 64
    float* ps  = kvs + 64 * 64;      // 64 x 34
    float* ws  = ps  + 64 * 34;      // 64 x 34
    float* ss  = ws  + 64 * 34;      // 2 x 64 x 34
    float* ssT = ss  + 2 * 64 * 34;  // 2 x 32 x 66
    const size_t base = (size_t)bh * T_LEN + bx * 64;
    const int tid = threadIdx.x;

    for (int i = tid; i < 64 * 64; i += 256) {
        int s = i >> 6, d = i & 63;
        kvs[i] = g_kv[(base + s) * 64 + d];
        qs[s * 66 + d] = g_q[(base + s) * 64 + d];
    }
    for (int i = tid; i < 64 * 32; i += 256) {
        int s = i >> 5, j = i & 31;
        ps[s * 34 + j] = g_pattn[base * 32 + i];
    }
    for (int i = tid; i < 2 * 64 * 32; i += 256) {
        int ci  = i >> 11;
        int idx = i & 2047;
        int d = idx >> 5, j = idx & 31;
        float v = g_S[((size_t)bh * NSC + 2 * bx + ci) * 2048 + idx];
        ss [ci * (64 * 34) + d * 34 + j] = v;
        ssT[ci * (32 * 66) + j * 66 + d] = v;
    }
    __syncthreads();

    const int cid = tid >> 7;
    const int lt  = (tid >> 2) & 31;
    const int sub = tid & 3;
    const int row = cid * 32 + lt;
    const int tgl = bx * 64 + row;
    const float inv = 1.0f / (float)(tgl + 1);
    const int smax = lt | 7;
    const float* ssb  = ss  + cid * (64 * 34);
    const float* ssTb = ssT + cid * (32 * 66);
    const int srow0 = cid * 32;

    // ---------------- pass 1 ----------------
    {
        const int j0  = sub * 8;
        const int dq0 = sub * 16;
        uint64_t qp[8];
        const uint64_t* qsp = (const uint64_t*)&qs[row * 66 + dq0];
#pragma unroll
        for (int k = 0; k < 8; k++) qp[k] = qsp[k];

        uint64_t rp[4] = {0ull, 0ull, 0ull, 0ull};

        // inter-chunk: q[t] @ S_prefix
        const float* qrow = &qs[row * 66];
#pragma unroll 8
        for (int d = 0; d < 64; d++) {
            uint64_t ap = pack2(qrow[d], qrow[d]);
            const uint64_t* sr = (const uint64_t*)&ssb[d * 34 + j0];
#pragma unroll
            for (int k = 0; k < 4; k++) rp[k] = fma2(ap, sr[k], rp[k]);
        }
        // intra-chunk causal
        for (int s = 0; s <= smax; s++) {
            const uint64_t* kr = (const uint64_t*)&kvs[(srow0 + s) * 64 + dq0];
            uint64_t d0a = 0ull, d1a = 0ull;
#pragma unroll
            for (int k = 0; k < 4; k++) {
                d0a = fma2(qp[2 * k],     kr[2 * k],     d0a);
                d1a = fma2(qp[2 * k + 1], kr[2 * k + 1], d1a);
            }
            float x0, y0, x1, y1;
            unpack2(d0a, x0, y0);
            unpack2(d1a, x1, y1);
            float a = (x0 + y0) + (x1 + y1);
            a += __shfl_xor_sync(0xffffffffu, a, 1);
            a += __shfl_xor_sync(0xffffffffu, a, 2);
            if (s <= lt) {
                uint64_t ap = pack2(a, a);
                const uint64_t* pr = (const uint64_t*)&ps[(srow0 + s) * 34 + j0];
#pragma unroll
                for (int k = 0; k < 4; k++) rp[k] = fma2(ap, pr[k], rp[k]);
            }
        }
        float r[8];
#pragma unroll
        for (int k = 0; k < 4; k++) unpack2(rp[k], r[2 * k], r[2 * k + 1]);
        float mx = -1e30f;
#pragma unroll
        for (int jj = 0; jj < 8; jj++) { r[jj] *= inv; mx = fmaxf(mx, r[jj]); }
        mx = fmaxf(mx, __shfl_xor_sync(0xffffffffu, mx, 1));
        mx = fmaxf(mx, __shfl_xor_sync(0xffffffffu, mx, 2));
        float sum = 0.f;
#pragma unroll
        for (int jj = 0; jj < 8; jj++) { r[jj] = expf(r[jj] - mx); sum += r[jj]; }
        sum += __shfl_xor_sync(0xffffffffu, sum, 1);
        sum += __shfl_xor_sync(0xffffffffu, sum, 2);
        float rs = 1.0f / sum;
#pragma unroll
        for (int jj = 0; jj < 8; jj++) ws[row * 34 + j0 + jj] = r[jj] * rs;
    }
    __syncwarp();

    // ---------------- pass 2 ----------------
    {
        const int d0 = sub * 16;
        const int jw0 = sub * 8;
        uint64_t wp[16];
        const uint64_t* wsp = (const uint64_t*)&ws[row * 34];
#pragma unroll
        for (int k = 0; k < 16; k++) wp[k] = wsp[k];

        uint64_t rp[8];
#pragma unroll
        for (int k = 0; k < 8; k++) rp[k] = 0ull;

        // inter-chunk: w[t] @ S^T_prefix
#pragma unroll 4
        for (int j2 = 0; j2 < 16; j2++) {
            float a0, a1;
            unpack2(wp[j2], a0, a1);
            uint64_t ap0 = pack2(a0, a0), ap1 = pack2(a1, a1);
            const uint64_t* sr0 = (const uint64_t*)&ssTb[(2 * j2)     * 66 + d0];
            const uint64_t* sr1 = (const uint64_t*)&ssTb[(2 * j2 + 1) * 66 + d0];
#pragma unroll
            for (int k = 0; k < 8; k++) {
                rp[k] = fma2(ap0, sr0[k], rp[k]);
                rp[k] = fma2(ap1, sr1[k], rp[k]);
            }
        }
        // intra-chunk causal
        const uint64_t* wq = &wp[jw0 >> 1];
        for (int s = 0; s <= smax; s++) {
            const uint64_t* pr = (const uint64_t*)&ps[(srow0 + s) * 34 + jw0];
            uint64_t da = 0ull;
#pragma unroll
            for (int k = 0; k < 4; k++) da = fma2(wq[k], pr[k], da);
            float x, y;
            unpack2(da, x, y);
            float a = x + y;
            a += __shfl_xor_sync(0xffffffffu, a, 1);
            a += __shfl_xor_sync(0xffffffffu, a, 2);
            if (s <= lt) {
                uint64_t ap = pack2(a, a);
                const uint64_t* kr = (const uint64_t*)&kvs[(srow0 + s) * 64 + d0];
#pragma unroll
                for (int k = 0; k < 8; k++) rp[k] = fma2(ap, kr[k], rp[k]);
            }
        }
        const int b = bh >> 4, hh = bh & 15;
        const size_t ob = ((size_t)tgl * 2 + b) * 1024 + hh * 64 + d0;
#pragma unroll
        for (int k = 0; k < 8; k++) {
            float x, y;
            unpack2(rp[k], x, y);
            g_ATh[ob + 2 * k]     = __float2half_rn(x * inv);
            g_ATh[ob + 2 * k + 1] = __float2half_rn(y * inv);
        }
    }
}

// ---------------------------------------------------------------------------
extern "C" void kernel_launch(void* const* d_in, const int* in_sizes, int n_in,
                              void* d_out, int out_size)
{
    const float* query  = (const float*)d_in[0];
    const float* pquery = (const float*)d_in[1];
    const float* Wpq = (const float*)d_in[2];
    const float* bpq = (const float*)d_in[3];
    const float* Wq  = (const float*)d_in[4];
    const float* bq  = (const float*)d_in[5];
    const float* Wpc = (const float*)d_in[6];
    const float* bpc = (const float*)d_in[7];
    const float* Wc  = (const float*)d_in[8];
    const float* bc  = (const float*)d_in[9];
    const float* Wo  = (const float*)d_in[10];
    const float* bo  = (const float*)d_in[11];
    float* out = (float*)d_out;

    float *p_pq, *p_q, *p_kp, *p_kv;
    __half *p_Ah, *p_PQh, *p_W4h, *p_WOh, *p_ATh;
    cudaGetSymbolAddress((void**)&p_pq,  g_pq);
    cudaGetSymbolAddress((void**)&p_q,   g_q);
    cudaGetSymbolAddress((void**)&p_kp,  g_kp);
    cudaGetSymbolAddress((void**)&p_kv,  g_kv);
    cudaGetSymbolAddress((void**)&p_Ah,  g_Ah);
    cudaGetSymbolAddress((void**)&p_PQh, g_PQh);
    cudaGetSymbolAddress((void**)&p_W4h, g_W4h);
    cudaGetSymbolAddress((void**)&p_WOh, g_WOh);
    cudaGetSymbolAddress((void**)&p_ATh, g_ATh);

    const int GEMM_SMEM = 3 * 32768;
    const int PL_SMEM = (64 * 66 + 32 * 66 + 64 * 64 + 64 * 32) * 4;
    const int FP_SMEM = (64 * 66 + 64 * 64 + 64 * 34 + 64 * 34 + 2 * 64 * 34 + 2 * 32 * 66) * 4;
    cudaFuncSetAttribute(gemm_mma,    cudaFuncAttributeMaxDynamicSharedMemorySize, GEMM_SMEM);
    cudaFuncSetAttribute(pattn_local, cudaFuncAttributeMaxDynamicSharedMemorySize, PL_SMEM);
    cudaFuncSetAttribute(fused_pass,  cudaFuncAttributeMaxDynamicSharedMemorySize, FP_SMEM);

    // ---- launch 0: ALL conversions ----
    CvtArgs ca;
    int acc = 0, n4;
    n4 = MROWS * E_DIM / 4;
    ca.s[0] = (const float4*)query;  ca.h[0] = (__half2*)p_Ah;  acc += n4; ca.end[0] = acc;
    n4 = 64 * E_DIM / 4;
    ca.s[1] = (const float4*)pquery; ca.h[1] = (__half2*)p_PQh; acc += n4; ca.end[1] = acc;
    n4 = NE / 4;
    ca.s[2] = (const float4*)Wq;  ca.h[2] = (__half2*)p_W4h;            acc += n4; ca.end[2] = acc;
    ca.s[3] = (const float4*)Wpc; ca.h[3] = (__half2*)(p_W4h + NE);     acc += n4; ca.end[3] = acc;
    ca.s[4] = (const float4*)Wc;  ca.h[4] = (__half2*)(p_W4h + 2 * NE); acc += n4; ca.end[4] = acc;
    ca.s[5] = (const float4*)Wpq; ca.h[5] = (__half2*)(p_W4h + 3 * NE); acc += n4; ca.end[5] = acc;
    ca.s[6] = (const float4*)Wo;  ca.h[6] = (__half2*)p_WOh;            acc += n4; ca.end[6] = acc;
    cvt_all<<<(acc + 255) / 256, 256>>>(ca);

    // ---- launch 1: q/kp/kv/pq projections (z = 0..3) ----
    gemm_mma<<<dim3(8, 32, 4), 256, GEMM_SMEM>>>(
        p_Ah, p_PQh, p_W4h,
        bq, bpc, bc, bpq,
        p_q, p_kp, p_kv, p_pq,
        SCALING, 1.0f, 1.0f, SCALING,
        MROWS, 64, 1, T_LEN, PLEN);

    // ---- launch 2: pattn + two 32-row local states per block ----
    pattn_local<<<dim3(T_LEN / 64, BH), 256, PL_SMEM>>>();

    // ---- launch 3: exclusive scan over 64 chunks ----
    scan_states<<<BH * 2048 / 256, 256>>>();

    // ---- launch 4: fused pass1 + softmax + pass2 ----
    fused_pass<<<dim3(T_LEN / 64, BH), 256, FP_SMEM>>>();

    // ---- launch 5: output projection -> d_out ----
    gemm_mma<<<dim3(8, 32, 1), 256, GEMM_SMEM>>>(
        p_ATh, p_ATh, p_WOh,
        bo, bo, bo, bo,
        out, out, out, out,
        1.0f, 1.0f, 1.0f, 1.0f,
        MROWS, MROWS, 0, 0, 0);
}